// round 14
// baseline (speedup 1.0000x reference)
#include <cuda_runtime.h>
#include <math.h>

#define BATCH 128
#define LSEQ 176
#define ROWS (BATCH*LSEQ)   /* 22528 */
#define DIN 20
#define DMODEL 256
#define DXZ 512
#define EPS 1e-5f

// ---------------- scratch (static device globals; no allocation) ----------------
__device__ float  g_h1[ROWS*DMODEL];     // after lin1+bn1+lrelu+LN
__device__ float  g_xz[ROWS*DXZ];        // in_proj output (u | z)
__device__ float2 g_dtxc[ROWS*DMODEL];   // {softplus(dt), conv+silu(xc)} interleaved
__device__ float  g_BC[ROWS*8];          // B[0..3], C[0..3] per row
__device__ float  g_yg[ROWS*DMODEL];     // scan output, gated
__device__ float  g_mo[ROWS*DMODEL];     // out_proj output with bn5 applied
__device__ float  g_flat[BATCH*2816];    // combined-tail output flattened
__device__ float  g_Wcomb[16*256];       // l5c_w @ l5b_w @ l5a_w
__device__ float  g_bcomb[16];           // l5c_w @ (l5b_w @ l5a_b + l5b_b) + l5c_b

// =====================================================================
// K1: lin1 (20->256) + bias, bn1 per-l affine, leaky_relu, LayerNorm(256)
// 256 threads, 16 rows per block.
// =====================================================================
__global__ void k_lin1_ln(const float* __restrict__ x,
                          const float* __restrict__ w, const float* __restrict__ b,
                          const float* __restrict__ bn_g, const float* __restrict__ bn_b,
                          const float* __restrict__ ln_g, const float* __restrict__ ln_b)
{
    __shared__ float w_sh[DMODEL*DIN];
    __shared__ float b_sh[DMODEL];
    __shared__ float x_sh[16*DIN];     // 16 rows x 20 = contiguous span of x
    __shared__ float red[8], red2[8];
    int t = threadIdx.x;
    for (int i = t; i < DMODEL*DIN; i += 256) w_sh[i] = w[i];
    for (int i = t; i < 16*DIN; i += 256)     x_sh[i] = x[blockIdx.x*16*DIN + i];
    b_sh[t] = b[t];
    float lng = ln_g[t], lnb = ln_b[t];
    __syncthreads();
    int wid = t >> 5;
    for (int r = 0; r < 16; r++) {
        int row = blockIdx.x*16 + r;
        float v = b_sh[t];
        #pragma unroll
        for (int i = 0; i < DIN; i++) v += x_sh[r*DIN + i]*w_sh[t*DIN+i];
        int l = row % LSEQ;
        v = v * (bn_g[l]*rsqrtf(1.f+EPS)) + bn_b[l];
        v = v > 0.f ? v : 0.01f*v;
        float s = v, s2 = v*v;
        #pragma unroll
        for (int o = 16; o > 0; o >>= 1) {
            s  += __shfl_xor_sync(0xFFFFFFFFu, s,  o);
            s2 += __shfl_xor_sync(0xFFFFFFFFu, s2, o);
        }
        if ((t & 31) == 0) { red[wid] = s; red2[wid] = s2; }
        __syncthreads();
        float a = 0.f, c = 0.f;
        #pragma unroll
        for (int i = 0; i < 8; i++) { a += red[i]; c += red2[i]; }
        float mu  = a*(1.f/256.f);
        float var = c*(1.f/256.f) - mu*mu;
        g_h1[row*DMODEL + t] = (v - mu)*rsqrtf(var + EPS)*lng + lnb;
        __syncthreads();
    }
}

// =====================================================================
// SGEMM: C[M,N] = A[M,K] @ W[N,K]^T ; BM x 128 tile, BK=16, (BM/16)x8
// microtile, 2-stage smem double buffering, XOR-swizzled tiles.
// BM=128: 2 CTAs/SM (regs<=128, 32KB smem). BM=64: 3 CTAs/SM (regs<=85,
// 24KB smem) -> 444 slots, cuts wave quantization on the out_proj grid.
// EPI 0: none; 2: per-row affine val*scale[m%L]+shift[m%L]
// =====================================================================
template<int EPI, int BM>
__global__ void __launch_bounds__(256, (BM == 128 ? 2 : 3))
sgemm(const float* __restrict__ A, const float* __restrict__ W,
      float* __restrict__ C, int M, int N, int K,
      const float* __restrict__ rs, const float* __restrict__ rb)
{
    constexpr int MI = BM/16;          // rows per thread: 8 (BM=128) or 4 (BM=64)
    __shared__ float As[2][16*BM];     // swizzled [k][m]
    __shared__ float Bs[2][16*128];    // swizzled [k][n]
    const int tid = threadIdx.x;
    const int tx = tid & 15, ty = tid >> 4;
    const int m0 = blockIdx.x * BM;
    const int n0 = blockIdx.y * 128;
    // per-thread load coordinates (float4 quads)
    const int lr0 = tid >> 2,           lc0 = (tid & 3) * 4;
    const int lr1 = (tid + 256) >> 2,   lc1 = lc0;
    // store columns after swizzle ((lc+i)>>2 == lc>>2 for i<4)
    const int sc0 = lr0 ^ ((lc0 >> 2) << 3);
    const int sc1 = lr1 ^ ((lc1 >> 2) << 3);

    float acc[MI][8];
    #pragma unroll
    for (int i = 0; i < MI; i++)
        #pragma unroll
        for (int j = 0; j < 8; j++) acc[i][j] = 0.f;

    float4 pa0, pa1, pw0, pw1;

    // prologue: load tile 0 into registers, store to buffer 0
    pa0 = *(const float4*)(A + (size_t)(m0+lr0)*K + lc0);
    if (BM == 128) pa1 = *(const float4*)(A + (size_t)(m0+lr1)*K + lc1);
    pw0 = *(const float4*)(W + (size_t)(n0+lr0)*K + lc0);
    pw1 = *(const float4*)(W + (size_t)(n0+lr1)*K + lc1);
    {
        float* as = As[0]; float* bs = Bs[0];
        as[(lc0+0)*BM + sc0] = pa0.x; as[(lc0+1)*BM + sc0] = pa0.y;
        as[(lc0+2)*BM + sc0] = pa0.z; as[(lc0+3)*BM + sc0] = pa0.w;
        if (BM == 128) {
            as[(lc1+0)*BM + sc1] = pa1.x; as[(lc1+1)*BM + sc1] = pa1.y;
            as[(lc1+2)*BM + sc1] = pa1.z; as[(lc1+3)*BM + sc1] = pa1.w;
        }
        bs[(lc0+0)*128 + sc0] = pw0.x; bs[(lc0+1)*128 + sc0] = pw0.y;
        bs[(lc0+2)*128 + sc0] = pw0.z; bs[(lc0+3)*128 + sc0] = pw0.w;
        bs[(lc1+0)*128 + sc1] = pw1.x; bs[(lc1+1)*128 + sc1] = pw1.y;
        bs[(lc1+2)*128 + sc1] = pw1.z; bs[(lc1+3)*128 + sc1] = pw1.w;
    }
    __syncthreads();

    const int T = K >> 4;
    for (int t = 0; t < T; t++) {
        // prefetch tile t+1 into registers (overlaps with compute below)
        if (t + 1 < T) {
            int k0 = (t + 1) << 4;
            pa0 = *(const float4*)(A + (size_t)(m0+lr0)*K + k0 + lc0);
            if (BM == 128) pa1 = *(const float4*)(A + (size_t)(m0+lr1)*K + k0 + lc1);
            pw0 = *(const float4*)(W + (size_t)(n0+lr0)*K + k0 + lc0);
            pw1 = *(const float4*)(W + (size_t)(n0+lr1)*K + k0 + lc1);
        }
        // compute from current buffer
        const float* as = As[t & 1];
        const float* bs = Bs[t & 1];
        #pragma unroll
        for (int k = 0; k < 16; k++) {
            const int sw = (k >> 2) << 3;         // compile-time per unrolled k
            const int am = (ty*MI) ^ sw;
            const int bn2 = (tx*8) ^ sw;
            float a[MI], bv[8];
            #pragma unroll
            for (int i = 0; i < MI; i++) a[i] = as[k*BM + am + i];
            #pragma unroll
            for (int j = 0; j < 8; j++) bv[j] = bs[k*128 + bn2 + j];
            #pragma unroll
            for (int i = 0; i < MI; i++)
                #pragma unroll
                for (int j = 0; j < 8; j++) acc[i][j] += a[i]*bv[j];
        }
        // stage tile t+1 into the other buffer; single sync per iteration
        if (t + 1 < T) {
            float* asn = As[(t + 1) & 1]; float* bsn = Bs[(t + 1) & 1];
            asn[(lc0+0)*BM + sc0] = pa0.x; asn[(lc0+1)*BM + sc0] = pa0.y;
            asn[(lc0+2)*BM + sc0] = pa0.z; asn[(lc0+3)*BM + sc0] = pa0.w;
            if (BM == 128) {
                asn[(lc1+0)*BM + sc1] = pa1.x; asn[(lc1+1)*BM + sc1] = pa1.y;
                asn[(lc1+2)*BM + sc1] = pa1.z; asn[(lc1+3)*BM + sc1] = pa1.w;
            }
            bsn[(lc0+0)*128 + sc0] = pw0.x; bsn[(lc0+1)*128 + sc0] = pw0.y;
            bsn[(lc0+2)*128 + sc0] = pw0.z; bsn[(lc0+3)*128 + sc0] = pw0.w;
            bsn[(lc1+0)*128 + sc1] = pw1.x; bsn[(lc1+1)*128 + sc1] = pw1.y;
            bsn[(lc1+2)*128 + sc1] = pw1.z; bsn[(lc1+3)*128 + sc1] = pw1.w;
            __syncthreads();
        }
    }

    const int n = n0 + tx*8;
    #pragma unroll
    for (int i = 0; i < MI; i++) {
        int m = m0 + ty*MI + i;
        float sc = 1.f, sb = 0.f;
        if (EPI == 2) { int l = m % LSEQ; sc = rs[l]*rsqrtf(1.f+EPS); sb = rb[l]; }
        float4 o0, o1;
        o0.x = acc[i][0]*sc + sb;
        o0.y = acc[i][1]*sc + sb;
        o0.z = acc[i][2]*sc + sb;
        o0.w = acc[i][3]*sc + sb;
        o1.x = acc[i][4]*sc + sb;
        o1.y = acc[i][5]*sc + sb;
        o1.z = acc[i][6]*sc + sb;
        o1.w = acc[i][7]*sc + sb;
        *(float4*)(C + (size_t)m*N + n)     = o0;
        *(float4*)(C + (size_t)m*N + n + 4) = o1;
    }
}

// =====================================================================
// K3: conv(k=2)+SiLU -> xc ; dbl = xc @ x_proj^T (24) ; dt = softplus(dtr@dt_proj^T + b)
// 256 threads, 16 rows/block. dt and xc written interleaved (float2) for the scan.
// =====================================================================
__global__ void k_conv_proj(const float* __restrict__ conv_w, const float* __restrict__ conv_b,
                            const float* __restrict__ x_proj_w,
                            const float* __restrict__ dt_proj_w, const float* __restrict__ dt_proj_b)
{
    __shared__ float xw[24*256];
    __shared__ float dtw[16*256];   // transposed: dtw[i*256+t] = dt_proj_w[t*16+i]
    __shared__ float w0[256], w1[256], cb[256], dtb[256];
    __shared__ float xc_sh[256];
    __shared__ float dtr_sh[16];
    int t = threadIdx.x;
    for (int i = t; i < 24*256; i += 256) xw[i] = x_proj_w[i];
    #pragma unroll
    for (int i = 0; i < 16; i++) dtw[i*256 + t] = dt_proj_w[t*16 + i];
    w0[t] = conv_w[t*2]; w1[t] = conv_w[t*2+1];
    cb[t] = conv_b[t];   dtb[t] = dt_proj_b[t];
    __syncthreads();
    int wid = t >> 5, lane = t & 31;
    for (int r = 0; r < 16; r++) {
        int row = blockIdx.x*16 + r;
        int l = row % LSEQ;
        float u  = g_xz[(size_t)row*DXZ + t];
        float up = (l > 0) ? g_xz[(size_t)(row-1)*DXZ + t] : 0.f;
        float pre = up*w0[t] + u*w1[t] + cb[t];
        float xcv = pre / (1.f + __expf(-pre));
        xc_sh[t] = xcv;
        __syncthreads();
        #pragma unroll
        for (int oi = 0; oi < 3; oi++) {
            int o = wid*3 + oi;
            float p = 0.f;
            #pragma unroll
            for (int i = lane; i < 256; i += 32) p += xc_sh[i]*xw[o*256 + i];
            #pragma unroll
            for (int off = 16; off > 0; off >>= 1) p += __shfl_down_sync(0xFFFFFFFFu, p, off);
            if (lane == 0) {
                if (o < 16) dtr_sh[o] = p;
                else        g_BC[row*8 + (o - 16)] = p;
            }
        }
        __syncthreads();
        float acc = dtb[t];
        #pragma unroll
        for (int i = 0; i < 16; i++) acc += dtr_sh[i]*dtw[i*256 + t];
        float dtv = (acc > 20.f) ? acc : log1pf(__expf(acc));
        g_dtxc[row*DMODEL + t] = make_float2(dtv, xcv);
        __syncthreads();
    }
}

// =====================================================================
// K4: selective scan over L, thread = (b, d-quarter); D-skip + SiLU(z) gate.
// Grid = BATCH*4 x 64 threads (3-4 CTAs/SM); prefetch distance 2.
// =====================================================================
__global__ void k_scan(const float* __restrict__ A_log, const float* __restrict__ Dp)
{
    int b = blockIdx.x >> 2;
    int d = ((blockIdx.x & 3) << 6) + threadIdx.x;
    float A0 = -__expf(A_log[d*4+0]);
    float A1 = -__expf(A_log[d*4+1]);
    float A2 = -__expf(A_log[d*4+2]);
    float A3 = -__expf(A_log[d*4+3]);
    float dp = Dp[d];
    float h0 = 0.f, h1 = 0.f, h2 = 0.f, h3 = 0.f;
    size_t base = (size_t)b*LSEQ;

    float2 c_dx = g_dtxc[base*DMODEL + d];
    float  c_zv = g_xz[base*DXZ + DMODEL + d];
    float4 c_B  = *(const float4*)(g_BC + base*8);
    float4 c_C  = *(const float4*)(g_BC + base*8 + 4);
    float2 n1_dx = {0.f,0.f}; float n1_zv = 0.f;
    float4 n1_B = {0.f,0.f,0.f,0.f}, n1_C = {0.f,0.f,0.f,0.f};
    {
        size_t r1 = base + 1;
        n1_dx = g_dtxc[r1*DMODEL + d];
        n1_zv = g_xz[r1*DXZ + DMODEL + d];
        n1_B  = *(const float4*)(g_BC + r1*8);
        n1_C  = *(const float4*)(g_BC + r1*8 + 4);
    }

    for (int l = 0; l < LSEQ; l++) {
        size_t row = base + l;
        float2 n2_dx = {0.f,0.f}; float n2_zv = 0.f;
        float4 n2_B = {0.f,0.f,0.f,0.f}, n2_C = {0.f,0.f,0.f,0.f};
        if (l + 2 < LSEQ) {
            size_t nr = row + 2;
            n2_dx = g_dtxc[nr*DMODEL + d];
            n2_zv = g_xz[nr*DXZ + DMODEL + d];
            n2_B  = *(const float4*)(g_BC + nr*8);
            n2_C  = *(const float4*)(g_BC + nr*8 + 4);
        }

        float dtv = c_dx.x, xcv = c_dx.y;
        float dx = dtv*xcv;
        h0 = h0*__expf(dtv*A0) + dx*c_B.x;
        h1 = h1*__expf(dtv*A1) + dx*c_B.y;
        h2 = h2*__expf(dtv*A2) + dx*c_B.z;
        h3 = h3*__expf(dtv*A3) + dx*c_B.w;
        float y = h0*c_C.x + h1*c_C.y + h2*c_C.z + h3*c_C.w + dp*xcv;
        float sz = c_zv / (1.f + __expf(-c_zv));
        g_yg[row*DMODEL + d] = y*sz;

        c_dx = n1_dx; c_zv = n1_zv; c_B = n1_B; c_C = n1_C;
        n1_dx = n2_dx; n1_zv = n2_zv; n1_B = n2_B; n1_C = n2_C;
    }
}

// =====================================================================
// K5a: precompute combined tail matrix (one block, 256 threads).
// (Wc@Wb)@Wa order: 8KB smem intermediate, 0.65M MACs.
// =====================================================================
__global__ void k_precomp(const float* __restrict__ l5a_w, const float* __restrict__ l5a_b,
                          const float* __restrict__ l5b_w, const float* __restrict__ l5b_b,
                          const float* __restrict__ l5c_w, const float* __restrict__ l5c_b)
{
    __shared__ float T0[16*128];   // Wc @ Wb  (8KB)
    __shared__ float tb1[64];      // Wb @ ba + bb
    int t = threadIdx.x;
    for (int idx = t; idx < 16*128; idx += 256) {
        int o = idx >> 7, k = idx & 127;
        float s = 0.f;
        for (int j = 0; j < 64; j++) s += l5c_w[o*64 + j]*l5b_w[j*128 + k];
        T0[idx] = s;
    }
    if (t < 64) {
        float s = l5b_b[t];
        for (int k = 0; k < 128; k++) s += l5b_w[t*128 + k]*l5a_b[k];
        tb1[t] = s;
    }
    __syncthreads();
    for (int idx = t; idx < 16*256; idx += 256) {
        int o = idx >> 8, c = idx & 255;
        float s = 0.f;
        for (int k = 0; k < 128; k++) s += T0[o*128 + k]*l5a_w[k*256 + c];
        g_Wcomb[idx] = s;
    }
    if (t < 16) {
        float s = l5c_b[t];
        for (int j = 0; j < 64; j++) s += l5c_w[t*64 + j]*tb1[j];
        g_bcomb[t] = s;
    }
}

// =====================================================================
// K5b: fused tail: y[16] = Wcomb @ mo_row + bcomb -> g_flat.
// 16 rows bulk-staged with float4 (one barrier per block, was 32);
// xs is read-only afterwards so the row loop is barrier-free.
// Smem reads xs[r*256 + seg + 16i]: 16 distinct banks x 2-lane
// broadcast per warp -> conflict-free.
// =====================================================================
__global__ void k_tail2()
{
    int t = threadIdx.x;
    int o = t >> 4, seg = t & 15;
    float wreg[16];
    #pragma unroll
    for (int i = 0; i < 16; i++) wreg[i] = g_Wcomb[o*256 + seg + 16*i];
    float bo = g_bcomb[o];
    __shared__ float xs[16*256];
    {
        const float4* src = (const float4*)(g_mo + (size_t)blockIdx.x*16*DMODEL);
        float4* dst = (float4*)xs;
        #pragma unroll
        for (int i = 0; i < 4; i++) dst[t + i*256] = src[t + i*256];
    }
    __syncthreads();
    int row0 = blockIdx.x*16;
    for (int r = 0; r < 16; r++) {
        float p = 0.f;
        #pragma unroll
        for (int i = 0; i < 16; i++) p += wreg[i]*xs[r*256 + seg + 16*i];
        #pragma unroll
        for (int off = 8; off > 0; off >>= 1) p += __shfl_down_sync(0xFFFFFFFFu, p, off, 16);
        if (seg == 0) {
            int row = row0 + r;
            int b = row / LSEQ, l = row % LSEQ;
            g_flat[b*2816 + l*16 + o] = p + bo;
        }
    }
}

// =====================================================================
// K7: fc3 (2816->15) + sigmoid; block per batch row, warp per output.
// float4-vectorized: 2816 = 128*22 -> 22 iterations of 2x LDG.128 + 4 FFMA.
// 480 threads = 15 warps, no dead warp.
// =====================================================================
__global__ void k_fc3(const float* __restrict__ w, const float* __restrict__ bias,
                      float* __restrict__ out)
{
    int b = blockIdx.x;
    int wid = threadIdx.x >> 5, lane = threadIdx.x & 31;
    const float4* f4 = (const float4*)(g_flat + b*2816);
    const float4* w4 = (const float4*)(w + wid*2816);
    float p = 0.f;
    #pragma unroll 4
    for (int i = lane; i < 704; i += 32) {   // 704 float4 = 2816 floats
        float4 fv = f4[i];
        float4 wv = w4[i];
        p += fv.x*wv.x + fv.y*wv.y + fv.z*wv.z + fv.w*wv.w;
    }
    #pragma unroll
    for (int o = 16; o > 0; o >>= 1) p += __shfl_down_sync(0xFFFFFFFFu, p, o);
    if (lane == 0) out[b*15 + wid] = 1.f/(1.f + __expf(-(p + bias[wid])));
}

// =====================================================================
extern "C" void kernel_launch(void* const* d_in, const int* in_sizes, int n_in,
                              void* d_out, int out_size)
{
    const float* x         = (const float*)d_in[0];
    const float* lin1_w    = (const float*)d_in[1];
    const float* lin1_b    = (const float*)d_in[2];
    const float* bn1_g     = (const float*)d_in[3];
    const float* bn1_b     = (const float*)d_in[4];
    const float* ln_g      = (const float*)d_in[5];
    const float* ln_b      = (const float*)d_in[6];
    const float* in_proj_w = (const float*)d_in[7];
    const float* conv_w    = (const float*)d_in[8];
    const float* conv_b    = (const float*)d_in[9];
    const float* x_proj_w  = (const float*)d_in[10];
    const float* dt_proj_w = (const float*)d_in[11];
    const float* dt_proj_b = (const float*)d_in[12];
    const float* A_log     = (const float*)d_in[13];
    const float* Dp        = (const float*)d_in[14];
    const float* out_proj_w= (const float*)d_in[15];
    const float* bn5_g     = (const float*)d_in[16];
    const float* bn5_b     = (const float*)d_in[17];
    const float* l5a_w     = (const float*)d_in[18];
    const float* l5a_b     = (const float*)d_in[19];
    const float* l5b_w     = (const float*)d_in[20];
    const float* l5b_b     = (const float*)d_in[21];
    const float* l5c_w     = (const float*)d_in[22];
    const float* l5c_b     = (const float*)d_in[23];
    const float* fc3_w     = (const float*)d_in[24];
    const float* fc3_b     = (const float*)d_in[25];
    float* out = (float*)d_out;

    float *p_h1, *p_xz, *p_yg, *p_mo;
    cudaGetSymbolAddress((void**)&p_h1,  g_h1);
    cudaGetSymbolAddress((void**)&p_xz,  g_xz);
    cudaGetSymbolAddress((void**)&p_yg,  g_yg);
    cudaGetSymbolAddress((void**)&p_mo,  g_mo);

    // 0. precompute combined tail matrix (tiny; ~2us)
    k_precomp<<<1, 256>>>(l5a_w, l5a_b, l5b_w, l5b_b, l5c_w, l5c_b);

    // 1. lin1 + bn1 + leaky_relu + LN
    k_lin1_ln<<<ROWS/16, 256>>>(x, lin1_w, lin1_b, bn1_g, bn1_b, ln_g, ln_b);

    // 2. in_proj: [ROWS,256] @ [512,256]^T -> g_xz   (BM=128, 2.38 waves @79% util)
    {
        dim3 g(ROWS/128, 512/128);
        sgemm<0,128><<<g, 256>>>(p_h1, in_proj_w, p_xz, ROWS, 512, 256, nullptr, nullptr);
    }

    // 3. conv + silu + x_proj + dt_proj
    k_conv_proj<<<ROWS/16, 256>>>(conv_w, conv_b, x_proj_w, dt_proj_w, dt_proj_b);

    // 4. scan (+ D skip + SiLU(z) gate)
    k_scan<<<BATCH*4, 64>>>(A_log, Dp);

    // 5. out_proj with fused bn5: BM=64 / 3 CTAs-per-SM variant kills the
    //    1.19-wave quantization of the 352-tile BM=128 grid (59% -> 79% util)
    {
        dim3 g(ROWS/64, 256/128);
        sgemm<2,64><<<g, 256>>>(p_yg, out_proj_w, p_mo, ROWS, 256, 256, bn5_g, bn5_b);
    }

    // 6. fused l5a+l5b+l5c via precomputed 16x256 matrix
    k_tail2<<<ROWS/16, 256>>>();

    // 7. fc3 + sigmoid (float4, 15 warps)
    k_fc3<<<BATCH, 480>>>(fc3_w, fc3_b, out);
}

// round 17
// speedup vs baseline: 1.1086x; 1.1086x over previous
#include <cuda_runtime.h>
#include <math.h>

#define BATCH 128
#define LSEQ 176
#define ROWS (BATCH*LSEQ)   /* 22528 */
#define DIN 20
#define DMODEL 256
#define DXZ 512
#define EPS 1e-5f

// ---------------- scratch (static device globals; no allocation) ----------------
__device__ float  g_h1[ROWS*DMODEL];     // after lin1+bn1+lrelu+LN
__device__ float  g_xz[ROWS*DXZ];        // in_proj output (u | z)
__device__ float2 g_dtxc[ROWS*DMODEL];   // {softplus(dt), conv+silu(xc)} interleaved
__device__ float  g_BC[ROWS*8];          // B[0..3], C[0..3] per row
__device__ float  g_yg[ROWS*DMODEL];     // scan output, gated
__device__ float  g_mo[ROWS*DMODEL];     // out_proj output with bn5 applied
__device__ float  g_flat[BATCH*2816];    // combined-tail output flattened
__device__ float  g_Wcomb[16*256];       // l5c_w @ l5b_w @ l5a_w
__device__ float  g_bcomb[16];           // l5c_w @ (l5b_w @ l5a_b + l5b_b) + l5c_b

// =====================================================================
// K1 (restructured): warp-per-row, barrier-free after staging.
// 8 warps x 4 rows (32 rows/block, grid 704). Lane owns channels
// lane+32j. w staged TRANSPOSED (w_sh[i*256+c]) so LDS bank = lane.
// LN stats via one 10-shfl butterfly; zero barriers in the row loop.
// =====================================================================
__global__ void k_lin1_ln(const float* __restrict__ x,
                          const float* __restrict__ w, const float* __restrict__ b,
                          const float* __restrict__ bn_g, const float* __restrict__ bn_b,
                          const float* __restrict__ ln_g, const float* __restrict__ ln_b)
{
    __shared__ float w_sh[DIN*DMODEL];   // transposed: w_sh[i*256+c] = w[c*DIN+i]
    __shared__ float b_sh[DMODEL], lng_sh[DMODEL], lnb_sh[DMODEL];
    __shared__ float x_sh[32*DIN];       // 32 rows x 20 = contiguous span of x
    int t = threadIdx.x;
    for (int idx = t; idx < DIN*DMODEL; idx += 256) {
        int i = idx >> 8, c = idx & 255;
        w_sh[idx] = w[c*DIN + i];
    }
    b_sh[t] = b[t]; lng_sh[t] = ln_g[t]; lnb_sh[t] = ln_b[t];
    for (int i = t; i < 32*DIN; i += 256) x_sh[i] = x[(size_t)blockIdx.x*32*DIN + i];
    __syncthreads();

    int wid = t >> 5, lane = t & 31;
    int base_row = blockIdx.x*32 + wid*4;

    for (int rr = 0; rr < 4; rr++) {
        int row = base_row + rr;
        int xoff = (wid*4 + rr)*DIN;
        int l = row % LSEQ;
        float bg = bn_g[l]*rsqrtf(1.f+EPS), bb = bn_b[l];

        float v[8];
        float s = 0.f, s2 = 0.f;
        #pragma unroll
        for (int j = 0; j < 8; j++) {
            int c = lane + 32*j;
            float acc = b_sh[c];
            #pragma unroll
            for (int i = 0; i < DIN; i++) acc += x_sh[xoff + i]*w_sh[i*256 + c];
            acc = acc*bg + bb;
            acc = acc > 0.f ? acc : 0.01f*acc;
            v[j] = acc;
            s += acc; s2 += acc*acc;
        }
        #pragma unroll
        for (int o = 16; o > 0; o >>= 1) {
            s  += __shfl_xor_sync(0xFFFFFFFFu, s,  o);
            s2 += __shfl_xor_sync(0xFFFFFFFFu, s2, o);
        }
        float mu  = s*(1.f/256.f);
        float var = s2*(1.f/256.f) - mu*mu;
        float inv = rsqrtf(var + EPS);
        #pragma unroll
        for (int j = 0; j < 8; j++) {
            int c = lane + 32*j;
            g_h1[(size_t)row*DMODEL + c] = (v[j] - mu)*inv*lng_sh[c] + lnb_sh[c];
        }
    }
}

// =====================================================================
// SGEMM: C[M,N] = A[M,K] @ W[N,K]^T ; BM x 128 tile, BK=16, (BM/16)x8
// microtile, 2-stage smem double buffering, XOR-swizzled tiles.
// BM=128: 2 CTAs/SM. BM=64: 3 CTAs/SM -> kills out_proj wave quantization.
// EPI 0: none; 2: per-row affine val*scale[m%L]+shift[m%L]
// =====================================================================
template<int EPI, int BM>
__global__ void __launch_bounds__(256, (BM == 128 ? 2 : 3))
sgemm(const float* __restrict__ A, const float* __restrict__ W,
      float* __restrict__ C, int M, int N, int K,
      const float* __restrict__ rs, const float* __restrict__ rb)
{
    constexpr int MI = BM/16;
    __shared__ float As[2][16*BM];
    __shared__ float Bs[2][16*128];
    const int tid = threadIdx.x;
    const int tx = tid & 15, ty = tid >> 4;
    const int m0 = blockIdx.x * BM;
    const int n0 = blockIdx.y * 128;
    const int lr0 = tid >> 2,           lc0 = (tid & 3) * 4;
    const int lr1 = (tid + 256) >> 2,   lc1 = lc0;
    const int sc0 = lr0 ^ ((lc0 >> 2) << 3);
    const int sc1 = lr1 ^ ((lc1 >> 2) << 3);

    float acc[MI][8];
    #pragma unroll
    for (int i = 0; i < MI; i++)
        #pragma unroll
        for (int j = 0; j < 8; j++) acc[i][j] = 0.f;

    float4 pa0, pa1, pw0, pw1;

    pa0 = *(const float4*)(A + (size_t)(m0+lr0)*K + lc0);
    if (BM == 128) pa1 = *(const float4*)(A + (size_t)(m0+lr1)*K + lc1);
    pw0 = *(const float4*)(W + (size_t)(n0+lr0)*K + lc0);
    pw1 = *(const float4*)(W + (size_t)(n0+lr1)*K + lc1);
    {
        float* as = As[0]; float* bs = Bs[0];
        as[(lc0+0)*BM + sc0] = pa0.x; as[(lc0+1)*BM + sc0] = pa0.y;
        as[(lc0+2)*BM + sc0] = pa0.z; as[(lc0+3)*BM + sc0] = pa0.w;
        if (BM == 128) {
            as[(lc1+0)*BM + sc1] = pa1.x; as[(lc1+1)*BM + sc1] = pa1.y;
            as[(lc1+2)*BM + sc1] = pa1.z; as[(lc1+3)*BM + sc1] = pa1.w;
        }
        bs[(lc0+0)*128 + sc0] = pw0.x; bs[(lc0+1)*128 + sc0] = pw0.y;
        bs[(lc0+2)*128 + sc0] = pw0.z; bs[(lc0+3)*128 + sc0] = pw0.w;
        bs[(lc1+0)*128 + sc1] = pw1.x; bs[(lc1+1)*128 + sc1] = pw1.y;
        bs[(lc1+2)*128 + sc1] = pw1.z; bs[(lc1+3)*128 + sc1] = pw1.w;
    }
    __syncthreads();

    const int T = K >> 4;
    for (int t = 0; t < T; t++) {
        if (t + 1 < T) {
            int k0 = (t + 1) << 4;
            pa0 = *(const float4*)(A + (size_t)(m0+lr0)*K + k0 + lc0);
            if (BM == 128) pa1 = *(const float4*)(A + (size_t)(m0+lr1)*K + k0 + lc1);
            pw0 = *(const float4*)(W + (size_t)(n0+lr0)*K + k0 + lc0);
            pw1 = *(const float4*)(W + (size_t)(n0+lr1)*K + k0 + lc1);
        }
        const float* as = As[t & 1];
        const float* bs = Bs[t & 1];
        #pragma unroll
        for (int k = 0; k < 16; k++) {
            const int sw = (k >> 2) << 3;
            const int am = (ty*MI) ^ sw;
            const int bn2 = (tx*8) ^ sw;
            float a[MI], bv[8];
            #pragma unroll
            for (int i = 0; i < MI; i++) a[i] = as[k*BM + am + i];
            #pragma unroll
            for (int j = 0; j < 8; j++) bv[j] = bs[k*128 + bn2 + j];
            #pragma unroll
            for (int i = 0; i < MI; i++)
                #pragma unroll
                for (int j = 0; j < 8; j++) acc[i][j] += a[i]*bv[j];
        }
        if (t + 1 < T) {
            float* asn = As[(t + 1) & 1]; float* bsn = Bs[(t + 1) & 1];
            asn[(lc0+0)*BM + sc0] = pa0.x; asn[(lc0+1)*BM + sc0] = pa0.y;
            asn[(lc0+2)*BM + sc0] = pa0.z; asn[(lc0+3)*BM + sc0] = pa0.w;
            if (BM == 128) {
                asn[(lc1+0)*BM + sc1] = pa1.x; asn[(lc1+1)*BM + sc1] = pa1.y;
                asn[(lc1+2)*BM + sc1] = pa1.z; asn[(lc1+3)*BM + sc1] = pa1.w;
            }
            bsn[(lc0+0)*128 + sc0] = pw0.x; bsn[(lc0+1)*128 + sc0] = pw0.y;
            bsn[(lc0+2)*128 + sc0] = pw0.z; bsn[(lc0+3)*128 + sc0] = pw0.w;
            bsn[(lc1+0)*128 + sc1] = pw1.x; bsn[(lc1+1)*128 + sc1] = pw1.y;
            bsn[(lc1+2)*128 + sc1] = pw1.z; bsn[(lc1+3)*128 + sc1] = pw1.w;
            __syncthreads();
        }
    }

    const int n = n0 + tx*8;
    #pragma unroll
    for (int i = 0; i < MI; i++) {
        int m = m0 + ty*MI + i;
        float sc = 1.f, sb = 0.f;
        if (EPI == 2) { int l = m % LSEQ; sc = rs[l]*rsqrtf(1.f+EPS); sb = rb[l]; }
        float4 o0, o1;
        o0.x = acc[i][0]*sc + sb;
        o0.y = acc[i][1]*sc + sb;
        o0.z = acc[i][2]*sc + sb;
        o0.w = acc[i][3]*sc + sb;
        o1.x = acc[i][4]*sc + sb;
        o1.y = acc[i][5]*sc + sb;
        o1.z = acc[i][6]*sc + sb;
        o1.w = acc[i][7]*sc + sb;
        *(float4*)(C + (size_t)m*N + n)     = o0;
        *(float4*)(C + (size_t)m*N + n + 4) = o1;
    }
}

// =====================================================================
// K3 (restructured): warp-per-row, barrier-free after weight staging.
// block = 8 warps x 4 rows each (grid 704). Per warp-row:
//   1. conv+SiLU into 8 regs (lane owns channels lane+32j; coalesced LDG)
//   2. 24 accumulators/lane over its 8 channels (conflict-free xw_sh LDS)
//   3. XOR-butterfly all-reduce: every lane holds all 24 sums in regs
//   4. lane 0 writes B/C (2x float4); dt computed per-lane from broadcast
//      dtr regs (conflict-free dtw_sh LDS), coalesced float2 store.
// smem: 24.5 + 16 + 4 = 44.5KB (< 48KB static limit).
// =====================================================================
__global__ void k_conv_proj(const float* __restrict__ conv_w, const float* __restrict__ conv_b,
                            const float* __restrict__ x_proj_w,
                            const float* __restrict__ dt_proj_w, const float* __restrict__ dt_proj_b)
{
    __shared__ float xw_sh[24*256];    // x_proj_w as-is: xw_sh[o*256+c]
    __shared__ float dtw_sh[16*256];   // transposed: dtw_sh[i*256+c] = dt_proj_w[c*16+i]
    __shared__ float w0s[256], w1s[256], cbs[256], dtbs[256];
    int t = threadIdx.x;
    for (int i = t; i < 24*256; i += 256) xw_sh[i] = x_proj_w[i];
    for (int i = t; i < 16*256; i += 256) {
        int ii = i >> 8, c = i & 255;
        dtw_sh[i] = dt_proj_w[c*16 + ii];
    }
    w0s[t] = conv_w[t*2]; w1s[t] = conv_w[t*2+1];
    cbs[t] = conv_b[t];   dtbs[t] = dt_proj_b[t];
    __syncthreads();

    int wid = t >> 5, lane = t & 31;
    int base_row = blockIdx.x*32 + wid*4;

    for (int rr = 0; rr < 4; rr++) {
        int row = base_row + rr;
        int l = row % LSEQ;

        float xc[8];
        #pragma unroll
        for (int j = 0; j < 8; j++) {
            int c = lane + 32*j;
            float u  = g_xz[(size_t)row*DXZ + c];
            float up = (l > 0) ? g_xz[(size_t)(row-1)*DXZ + c] : 0.f;
            float pre = up*w0s[c] + u*w1s[c] + cbs[c];
            xc[j] = pre / (1.f + __expf(-pre));
        }

        float accv[24];
        #pragma unroll
        for (int o = 0; o < 24; o++) accv[o] = 0.f;
        #pragma unroll
        for (int o = 0; o < 24; o++)
            #pragma unroll
            for (int j = 0; j < 8; j++)
                accv[o] += xc[j]*xw_sh[o*256 + lane + 32*j];

        #pragma unroll
        for (int off = 16; off > 0; off >>= 1)
            #pragma unroll
            for (int o = 0; o < 24; o++)
                accv[o] += __shfl_xor_sync(0xFFFFFFFFu, accv[o], off);

        if (lane == 0) {
            *(float4*)(g_BC + (size_t)row*8)     = make_float4(accv[16], accv[17], accv[18], accv[19]);
            *(float4*)(g_BC + (size_t)row*8 + 4) = make_float4(accv[20], accv[21], accv[22], accv[23]);
        }

        #pragma unroll
        for (int j = 0; j < 8; j++) {
            int c = lane + 32*j;
            float a = dtbs[c];
            #pragma unroll
            for (int i = 0; i < 16; i++) a += accv[i]*dtw_sh[i*256 + c];
            float dtv = (a > 20.f) ? a : log1pf(__expf(a));
            g_dtxc[(size_t)row*DMODEL + c] = make_float2(dtv, xc[j]);
        }
    }
}

// =====================================================================
// K4: selective scan over L, thread = (b, d-quarter); D-skip + SiLU(z) gate.
// Grid = BATCH*4 x 64 threads (3-4 CTAs/SM); prefetch distance 2.
// =====================================================================
__global__ void k_scan(const float* __restrict__ A_log, const float* __restrict__ Dp)
{
    int b = blockIdx.x >> 2;
    int d = ((blockIdx.x & 3) << 6) + threadIdx.x;
    float A0 = -__expf(A_log[d*4+0]);
    float A1 = -__expf(A_log[d*4+1]);
    float A2 = -__expf(A_log[d*4+2]);
    float A3 = -__expf(A_log[d*4+3]);
    float dp = Dp[d];
    float h0 = 0.f, h1 = 0.f, h2 = 0.f, h3 = 0.f;
    size_t base = (size_t)b*LSEQ;

    float2 c_dx = g_dtxc[base*DMODEL + d];
    float  c_zv = g_xz[base*DXZ + DMODEL + d];
    float4 c_B  = *(const float4*)(g_BC + base*8);
    float4 c_C  = *(const float4*)(g_BC + base*8 + 4);
    float2 n1_dx = {0.f,0.f}; float n1_zv = 0.f;
    float4 n1_B = {0.f,0.f,0.f,0.f}, n1_C = {0.f,0.f,0.f,0.f};
    {
        size_t r1 = base + 1;
        n1_dx = g_dtxc[r1*DMODEL + d];
        n1_zv = g_xz[r1*DXZ + DMODEL + d];
        n1_B  = *(const float4*)(g_BC + r1*8);
        n1_C  = *(const float4*)(g_BC + r1*8 + 4);
    }

    for (int l = 0; l < LSEQ; l++) {
        size_t row = base + l;
        float2 n2_dx = {0.f,0.f}; float n2_zv = 0.f;
        float4 n2_B = {0.f,0.f,0.f,0.f}, n2_C = {0.f,0.f,0.f,0.f};
        if (l + 2 < LSEQ) {
            size_t nr = row + 2;
            n2_dx = g_dtxc[nr*DMODEL + d];
            n2_zv = g_xz[nr*DXZ + DMODEL + d];
            n2_B  = *(const float4*)(g_BC + nr*8);
            n2_C  = *(const float4*)(g_BC + nr*8 + 4);
        }

        float dtv = c_dx.x, xcv = c_dx.y;
        float dx = dtv*xcv;
        h0 = h0*__expf(dtv*A0) + dx*c_B.x;
        h1 = h1*__expf(dtv*A1) + dx*c_B.y;
        h2 = h2*__expf(dtv*A2) + dx*c_B.z;
        h3 = h3*__expf(dtv*A3) + dx*c_B.w;
        float y = h0*c_C.x + h1*c_C.y + h2*c_C.z + h3*c_C.w + dp*xcv;
        float sz = c_zv / (1.f + __expf(-c_zv));
        g_yg[row*DMODEL + d] = y*sz;

        c_dx = n1_dx; c_zv = n1_zv; c_B = n1_B; c_C = n1_C;
        n1_dx = n2_dx; n1_zv = n2_zv; n1_B = n2_B; n1_C = n2_C;
    }
}

// =====================================================================
// K5a: precompute combined tail matrix (one block, 256 threads).
// (Wc@Wb)@Wa order: 8KB smem intermediate, 0.65M MACs.
// =====================================================================
__global__ void k_precomp(const float* __restrict__ l5a_w, const float* __restrict__ l5a_b,
                          const float* __restrict__ l5b_w, const float* __restrict__ l5b_b,
                          const float* __restrict__ l5c_w, const float* __restrict__ l5c_b)
{
    __shared__ float T0[16*128];   // Wc @ Wb  (8KB)
    __shared__ float tb1[64];      // Wb @ ba + bb
    int t = threadIdx.x;
    for (int idx = t; idx < 16*128; idx += 256) {
        int o = idx >> 7, k = idx & 127;
        float s = 0.f;
        for (int j = 0; j < 64; j++) s += l5c_w[o*64 + j]*l5b_w[j*128 + k];
        T0[idx] = s;
    }
    if (t < 64) {
        float s = l5b_b[t];
        for (int k = 0; k < 128; k++) s += l5b_w[t*128 + k]*l5a_b[k];
        tb1[t] = s;
    }
    __syncthreads();
    for (int idx = t; idx < 16*256; idx += 256) {
        int o = idx >> 8, c = idx & 255;
        float s = 0.f;
        for (int k = 0; k < 128; k++) s += T0[o*128 + k]*l5a_w[k*256 + c];
        g_Wcomb[idx] = s;
    }
    if (t < 16) {
        float s = l5c_b[t];
        for (int j = 0; j < 64; j++) s += l5c_w[t*64 + j]*tb1[j];
        g_bcomb[t] = s;
    }
}

// =====================================================================
// K5b: fused tail: y[16] = Wcomb @ mo_row + bcomb -> g_flat.
// 16 rows bulk-staged with float4 (one barrier per block).
// =====================================================================
__global__ void k_tail2()
{
    int t = threadIdx.x;
    int o = t >> 4, seg = t & 15;
    float wreg[16];
    #pragma unroll
    for (int i = 0; i < 16; i++) wreg[i] = g_Wcomb[o*256 + seg + 16*i];
    float bo = g_bcomb[o];
    __shared__ float xs[16*256];
    {
        const float4* src = (const float4*)(g_mo + (size_t)blockIdx.x*16*DMODEL);
        float4* dst = (float4*)xs;
        #pragma unroll
        for (int i = 0; i < 4; i++) dst[t + i*256] = src[t + i*256];
    }
    __syncthreads();
    int row0 = blockIdx.x*16;
    for (int r = 0; r < 16; r++) {
        float p = 0.f;
        #pragma unroll
        for (int i = 0; i < 16; i++) p += wreg[i]*xs[r*256 + seg + 16*i];
        #pragma unroll
        for (int off = 8; off > 0; off >>= 1) p += __shfl_down_sync(0xFFFFFFFFu, p, off, 16);
        if (seg == 0) {
            int row = row0 + r;
            int b = row / LSEQ, l = row % LSEQ;
            g_flat[b*2816 + l*16 + o] = p + bo;
        }
    }
}

// =====================================================================
// K7: fc3 (2816->15) + sigmoid; float4, 15 warps.
// =====================================================================
__global__ void k_fc3(const float* __restrict__ w, const float* __restrict__ bias,
                      float* __restrict__ out)
{
    int b = blockIdx.x;
    int wid = threadIdx.x >> 5, lane = threadIdx.x & 31;
    const float4* f4 = (const float4*)(g_flat + b*2816);
    const float4* w4 = (const float4*)(w + wid*2816);
    float p = 0.f;
    #pragma unroll 4
    for (int i = lane; i < 704; i += 32) {
        float4 fv = f4[i];
        float4 wv = w4[i];
        p += fv.x*wv.x + fv.y*wv.y + fv.z*wv.z + fv.w*wv.w;
    }
    #pragma unroll
    for (int o = 16; o > 0; o >>= 1) p += __shfl_down_sync(0xFFFFFFFFu, p, o);
    if (lane == 0) out[b*15 + wid] = 1.f/(1.f + __expf(-(p + bias[wid])));
}

// =====================================================================
extern "C" void kernel_launch(void* const* d_in, const int* in_sizes, int n_in,
                              void* d_out, int out_size)
{
    const float* x         = (const float*)d_in[0];
    const float* lin1_w    = (const float*)d_in[1];
    const float* lin1_b    = (const float*)d_in[2];
    const float* bn1_g     = (const float*)d_in[3];
    const float* bn1_b     = (const float*)d_in[4];
    const float* ln_g      = (const float*)d_in[5];
    const float* ln_b      = (const float*)d_in[6];
    const float* in_proj_w = (const float*)d_in[7];
    const float* conv_w    = (const float*)d_in[8];
    const float* conv_b    = (const float*)d_in[9];
    const float* x_proj_w  = (const float*)d_in[10];
    const float* dt_proj_w = (const float*)d_in[11];
    const float* dt_proj_b = (const float*)d_in[12];
    const float* A_log     = (const float*)d_in[13];
    const float* Dp        = (const float*)d_in[14];
    const float* out_proj_w= (const float*)d_in[15];
    const float* bn5_g     = (const float*)d_in[16];
    const float* bn5_b     = (const float*)d_in[17];
    const float* l5a_w     = (const float*)d_in[18];
    const float* l5a_b     = (const float*)d_in[19];
    const float* l5b_w     = (const float*)d_in[20];
    const float* l5b_b     = (const float*)d_in[21];
    const float* l5c_w     = (const float*)d_in[22];
    const float* l5c_b     = (const float*)d_in[23];
    const float* fc3_w     = (const float*)d_in[24];
    const float* fc3_b     = (const float*)d_in[25];
    float* out = (float*)d_out;

    float *p_h1, *p_xz, *p_yg, *p_mo;
    cudaGetSymbolAddress((void**)&p_h1,  g_h1);
    cudaGetSymbolAddress((void**)&p_xz,  g_xz);
    cudaGetSymbolAddress((void**)&p_yg,  g_yg);
    cudaGetSymbolAddress((void**)&p_mo,  g_mo);

    // 0. precompute combined tail matrix (tiny; ~2us)
    k_precomp<<<1, 256>>>(l5a_w, l5a_b, l5b_w, l5b_b, l5c_w, l5c_b);

    // 1. lin1 + bn1 + leaky_relu + LN (warp-per-row, barrier-free)
    k_lin1_ln<<<ROWS/32, 256>>>(x, lin1_w, lin1_b, bn1_g, bn1_b, ln_g, ln_b);

    // 2. in_proj: [ROWS,256] @ [512,256]^T -> g_xz
    {
        dim3 g(ROWS/128, 512/128);
        sgemm<0,128><<<g, 256>>>(p_h1, in_proj_w, p_xz, ROWS, 512, 256, nullptr, nullptr);
    }

    // 3. conv + silu + x_proj + dt_proj (warp-per-row, barrier-free)
    k_conv_proj<<<ROWS/32, 256>>>(conv_w, conv_b, x_proj_w, dt_proj_w, dt_proj_b);

    // 4. scan (+ D skip + SiLU(z) gate)
    k_scan<<<BATCH*4, 64>>>(A_log, Dp);

    // 5. out_proj with fused bn5 (BM=64, 3 CTAs/SM)
    {
        dim3 g(ROWS/64, 256/128);
        sgemm<2,64><<<g, 256>>>(p_yg, out_proj_w, p_mo, ROWS, 256, 256, bn5_g, bn5_b);
    }

    // 6. fused l5a+l5b+l5c via precomputed 16x256 matrix
    k_tail2<<<ROWS/16, 256>>>();

    // 7. fc3 + sigmoid (float4, 15 warps)
    k_fc3<<<BATCH, 480>>>(fc3_w, fc3_b, out);
}